// round 15
// baseline (speedup 1.0000x reference)
#include <cuda_runtime.h>
#include <cuda_fp16.h>
#include <cstdint>
#include <math.h>

// ---------------------------------------------------------------------------
// RoPE-LoFTR encoder layer. mma.sync fp16 GEMMs (fp32 accum), ldmatrix,
// cp.async rings, RoPE fused in q/k epilogues (table-based), LayerNorms fused
// into the Wm and W2 GEMM epilogues, register-resident KV attention.
// N=4, L=16384 (128x128), C=256, NHEAD=8, D=32.
// ---------------------------------------------------------------------------

#define MAXM   65536
#define CDIM   256
#define LSEQ   16384
#define NHEADS 8
#define NCHUNK 32

typedef __half hf;

// fp32 buffers
__device__ float g_kvp[(size_t)NCHUNK * 32 * 32 * 32];
__device__ float g_ksp[(size_t)NCHUNK * 32 * 32];
__device__ float g_kv [(size_t)32 * 32 * 32];
__device__ float g_ksum[(size_t)32 * 32];
__device__ float2 g_rope[128 * 8];    // (pos-1, freq) -> {sin, cos}

// fp16 buffers
__device__ hf g_qh [(size_t)MAXM * CDIM];
__device__ hf g_kh [(size_t)MAXM * CDIM];
__device__ hf g_vh [(size_t)MAXM * CDIM];
__device__ hf g_xh [(size_t)MAXM * CDIM];
__device__ hf g_sh [(size_t)MAXM * CDIM];
__device__ hf g_mh [(size_t)MAXM * CDIM];
__device__ hf g_t1h[(size_t)MAXM * CDIM];
__device__ hf g_h1h[(size_t)MAXM * 2 * CDIM];
// fp16 weights
__device__ hf g_wq[CDIM * CDIM];
__device__ hf g_wk[CDIM * CDIM];
__device__ hf g_wv[CDIM * CDIM];
__device__ hf g_wm[CDIM * CDIM];
__device__ hf g_w1[2 * CDIM * 2 * CDIM];
__device__ hf g_w2[CDIM * 2 * CDIM];

// ---------------------------------------------------------------------------
#define CP_ASYNC16(dst, src) \
    asm volatile("cp.async.cg.shared.global [%0], [%1], 16;" \
                 :: "r"(dst), "l"(src) : "memory")
#define CP_COMMIT() asm volatile("cp.async.commit_group;" ::: "memory")
#define CP_WAIT(n)  asm volatile("cp.async.wait_group %0;" :: "n"(n) : "memory")

#define LDMATRIX_X4(r0, r1, r2, r3, addr) \
    asm volatile("ldmatrix.sync.aligned.m8n8.x4.shared.b16 {%0,%1,%2,%3}, [%4];" \
                 : "=r"(r0), "=r"(r1), "=r"(r2), "=r"(r3) : "r"(addr))

__device__ __forceinline__ uint32_t smem_u32(const void* p) {
    uint32_t a;
    asm("{ .reg .u64 t; cvta.to.shared.u64 t, %1; cvt.u32.u64 %0, t; }"
        : "=r"(a) : "l"(p));
    return a;
}

__device__ __forceinline__ void mma16816(float* c, const uint32_t* a,
                                         const uint32_t* b) {
    asm volatile(
        "mma.sync.aligned.m16n8k16.row.col.f32.f16.f16.f32 "
        "{%0,%1,%2,%3}, {%4,%5,%6,%7}, {%8,%9}, {%0,%1,%2,%3};"
        : "+f"(c[0]), "+f"(c[1]), "+f"(c[2]), "+f"(c[3])
        : "r"(a[0]), "r"(a[1]), "r"(a[2]), "r"(a[3]), "r"(b[0]), "r"(b[1]));
}

// smem tile rows x 32 fp16 (64B/row); 16B chunk swizzle: ch ^= (row>>1)&3
__device__ __forceinline__ uint32_t tile_off(int row, int ch) {
    return (uint32_t)(row * 64 + ((ch ^ ((row >> 1) & 3)) << 4));
}

__device__ __forceinline__ uint32_t pack_h2(float f0, float f1) {
    hf h0 = __float2half_rn(f0);
    hf h1 = __float2half_rn(f1);
    return (uint32_t)__half_as_ushort(h1) << 16 |
           (uint32_t)__half_as_ushort(h0);
}

// ---------------------------------------------------------------------------
// RoPE table init: angle = pos * exp(-f * ln(10000)/8), pos in 1..128.
// ---------------------------------------------------------------------------
__global__ void rope_init()
{
    int i = threadIdx.x;          // 0..1023
    int p = i >> 3, f = i & 7;
    float ang = (float)(p + 1) * expf(-(float)f * 1.1512925465f);
    float s, c;
    sincosf(ang, &s, &c);
    g_rope[i] = make_float2(s, c);
}

// ---------------------------------------------------------------------------
// GEMM: C[M,N] = A[M,K] @ B[N,K]^T; fp16 in, fp32 accum.
// Tile 128x128, BK=32, 256 threads (8 warps, 4m x 2n), 4-stage cp.async ring.
// OMODE 1: fp16 out (optional RELU). OMODE 2: elu+1 + RoPE, fp16 out (N=256).
// A switches to A2 at k=Ksplit (concat GEMM).
// ---------------------------------------------------------------------------
#define STAGES 4
#define STAGE_BYTES 16384

template <int OMODE, bool RELU>
__global__ __launch_bounds__(256) void gemm_mma(
    const hf* __restrict__ A, int lda,
    const hf* __restrict__ A2, int lda2, int Ksplit,
    const hf* __restrict__ B,
    hf* __restrict__ Ch,
    int M, int N, int K)
{
    extern __shared__ char smem[];

    const int tid  = threadIdx.x;
    const int lane = tid & 31;
    const int wid  = tid >> 5;
    const int g    = lane >> 2;
    const int tig  = lane & 3;
    const int wm   = wid & 3;
    const int wn   = wid >> 2;
    const int bm   = blockIdx.y * 128;
    const int bn   = blockIdx.x * 128;
    const int nkc  = K / 32;

    const int a_lrow  = lane & 15;
    const int a_khalf = lane >> 4;
    const int b_lrow  = lane & 7;
    const int b_kpart = (lane >> 3) & 1;
    const int b_npart = lane >> 4;

    float acc[2][8][4];
#pragma unroll
    for (int i = 0; i < 2; i++)
#pragma unroll
        for (int j = 0; j < 8; j++)
#pragma unroll
            for (int e = 0; e < 4; e++) acc[i][j][e] = 0.f;

    const int slot0 = tid, slot1 = tid + 256;

    auto issue = [&](int kc) {
        const int stg = kc & (STAGES - 1);
        const int kin = kc * 32;
        const hf* Asrc; int ald, koff;
        if (kin < Ksplit) { Asrc = A;  ald = lda;  koff = kin; }
        else              { Asrc = A2; ald = lda2; koff = kin - Ksplit; }

        uint32_t sA = smem_u32(smem + stg * STAGE_BYTES);
        uint32_t sB = sA + 8192;
        {
            int row = slot0 >> 2, ch = slot0 & 3;
            CP_ASYNC16(sA + tile_off(row, ch),
                       Asrc + (size_t)(bm + row) * ald + koff + ch * 8);
        }
        {
            int row = slot1 >> 2, ch = slot1 & 3;
            CP_ASYNC16(sA + tile_off(row, ch),
                       Asrc + (size_t)(bm + row) * ald + koff + ch * 8);
        }
        {
            int row = slot0 >> 2, ch = slot0 & 3;
            CP_ASYNC16(sB + tile_off(row, ch),
                       B + (size_t)(bn + row) * K + kin + ch * 8);
        }
        {
            int row = slot1 >> 2, ch = slot1 & 3;
            CP_ASYNC16(sB + tile_off(row, ch),
                       B + (size_t)(bn + row) * K + kin + ch * 8);
        }
        CP_COMMIT();
    };

    issue(0); issue(1); issue(2);

    for (int kc = 0; kc < nkc; kc++) {
        CP_WAIT(2);
        __syncthreads();
        if (kc + 3 < nkc) issue(kc + 3);
        else CP_COMMIT();

        const uint32_t sA = smem_u32(smem + (kc & (STAGES - 1)) * STAGE_BYTES);
        const uint32_t sB = sA + 8192;

#pragma unroll
        for (int s = 0; s < 2; s++) {
            uint32_t af[2][4];
#pragma unroll
            for (int mi = 0; mi < 2; mi++) {
                int r  = wm * 32 + mi * 16 + a_lrow;
                int ch = 2 * s + a_khalf;
                LDMATRIX_X4(af[mi][0], af[mi][1], af[mi][2], af[mi][3],
                            sA + tile_off(r, ch));
            }
            uint32_t bfr[8][2];
#pragma unroll
            for (int njp = 0; njp < 4; njp++) {
                int r  = wn * 64 + (2 * njp + b_npart) * 8 + b_lrow;
                int ch = 2 * s + b_kpart;
                LDMATRIX_X4(bfr[2 * njp][0], bfr[2 * njp][1],
                            bfr[2 * njp + 1][0], bfr[2 * njp + 1][1],
                            sB + tile_off(r, ch));
            }
#pragma unroll
            for (int mi = 0; mi < 2; mi++)
#pragma unroll
                for (int nj = 0; nj < 8; nj++)
                    mma16816(acc[mi][nj], af[mi], bfr[nj]);
        }
    }

    // epilogue
#pragma unroll
    for (int mi = 0; mi < 2; mi++) {
        int rbase = bm + wm * 32 + mi * 16 + g;
#pragma unroll
        for (int nj = 0; nj < 8; nj++) {
            int col = bn + wn * 64 + nj * 8 + 2 * tig;
            float c0 = acc[mi][nj][0], c1 = acc[mi][nj][1];
            float c2 = acc[mi][nj][2], c3 = acc[mi][nj][3];
            if (OMODE == 2) {
                // elu+1 then RoPE via table; (col, col+1) is a rotate pair
                int rem = col >> 1;            // 0..127 (N == 256)
                int tt  = rem & 15;
                int qf  = tt >> 1;
                bool odd = (tt & 1) != 0;
#pragma unroll
                for (int rr = 0; rr < 2; rr++) {
                    int r = rbase + rr * 8;
                    int l = r & (LSEQ - 1);
                    int p = odd ? (l & 127) : (l >> 7);
                    float2 sc = g_rope[p * 8 + qf];
                    float u0 = rr ? c2 : c0;
                    float u1 = rr ? c3 : c1;
                    float x0 = u0 > 0.f ? u0 + 1.f : __expf(u0);
                    float x1 = u1 > 0.f ? u1 + 1.f : __expf(u1);
                    *(uint32_t*)(Ch + (size_t)r * N + col) =
                        pack_h2(x0 * sc.y - x1 * sc.x, x1 * sc.y + x0 * sc.x);
                }
            } else {
                if (RELU) {
                    c0 = fmaxf(c0, 0.f); c1 = fmaxf(c1, 0.f);
                    c2 = fmaxf(c2, 0.f); c3 = fmaxf(c3, 0.f);
                }
                *(uint32_t*)(Ch + (size_t)rbase * N + col)       = pack_h2(c0, c1);
                *(uint32_t*)(Ch + (size_t)(rbase + 8) * N + col) = pack_h2(c2, c3);
            }
        }
    }
}

// ---------------------------------------------------------------------------
// GEMM + fused LayerNorm. C = LN(A @ B^T) over N=256 (full row per block).
// Tile 128x256, BK=32, 512 threads (16 warps, 4m x 4n), 4-stage cp.async.
// FINAL=false: write fp16 (LN1 -> t1h). FINAL=true: out = resid + LN, fp32.
// ---------------------------------------------------------------------------
#define LSTAGES 4
#define LSTAGE_BYTES 24576   // A 8KB + B 16KB
#define LN_SMEM (LSTAGES * LSTAGE_BYTES + 2 * 1024 + 2 * 2048)

template <bool FINAL>
__global__ __launch_bounds__(512) void gemm_ln(
    const hf* __restrict__ A, const hf* __restrict__ B,
    const float* __restrict__ gw, const float* __restrict__ bw,
    const float* __restrict__ resid,
    float* __restrict__ outf, hf* __restrict__ outh,
    int M, int K)
{
    extern __shared__ char smem[];
    float* sg   = (float*)(smem + LSTAGES * LSTAGE_BYTES);
    float* sb   = sg + 256;
    float* rsum = sb + 256;          // [128][4]
    float* rsq  = rsum + 512;        // [128][4]

    const int N = 256;
    const int tid  = threadIdx.x;
    const int lane = tid & 31;
    const int wid  = tid >> 5;
    const int g    = lane >> 2;
    const int tig  = lane & 3;
    const int wm   = wid & 3;
    const int wn   = wid >> 2;       // 0..3
    const int bm   = blockIdx.x * 128;
    const int nkc  = K / 32;

    const int a_lrow  = lane & 15;
    const int a_khalf = lane >> 4;
    const int b_lrow  = lane & 7;
    const int b_kpart = (lane >> 3) & 1;
    const int b_npart = lane >> 4;

    if (tid < 256) { sg[tid] = gw[tid]; sb[tid] = bw[tid]; }

    float acc[2][8][4];
#pragma unroll
    for (int i = 0; i < 2; i++)
#pragma unroll
        for (int j = 0; j < 8; j++)
#pragma unroll
            for (int e = 0; e < 4; e++) acc[i][j][e] = 0.f;

    auto issue = [&](int kc) {
        const int stg = kc & (LSTAGES - 1);
        const int kin = kc * 32;
        uint32_t sA = smem_u32(smem + stg * LSTAGE_BYTES);
        uint32_t sB = sA + 8192;
        {
            int row = tid >> 2, ch = tid & 3;
            CP_ASYNC16(sA + tile_off(row, ch),
                       A + (size_t)(bm + row) * K + kin + ch * 8);
        }
        {
            int row = tid >> 2, ch = tid & 3;
            CP_ASYNC16(sB + tile_off(row, ch),
                       B + (size_t)row * K + kin + ch * 8);
            int slot = tid + 512;
            int row2 = slot >> 2, ch2 = slot & 3;
            CP_ASYNC16(sB + tile_off(row2, ch2),
                       B + (size_t)row2 * K + kin + ch2 * 8);
        }
        CP_COMMIT();
    };

    issue(0); issue(1); issue(2);

    for (int kc = 0; kc < nkc; kc++) {
        CP_WAIT(2);
        __syncthreads();
        if (kc + 3 < nkc) issue(kc + 3);
        else CP_COMMIT();

        const uint32_t sA = smem_u32(smem + (kc & (LSTAGES - 1)) * LSTAGE_BYTES);
        const uint32_t sB = sA + 8192;

#pragma unroll
        for (int s = 0; s < 2; s++) {
            uint32_t af[2][4];
#pragma unroll
            for (int mi = 0; mi < 2; mi++) {
                int r  = wm * 32 + mi * 16 + a_lrow;
                int ch = 2 * s + a_khalf;
                LDMATRIX_X4(af[mi][0], af[mi][1], af[mi][2], af[mi][3],
                            sA + tile_off(r, ch));
            }
            uint32_t bfr[8][2];
#pragma unroll
            for (int njp = 0; njp < 4; njp++) {
                int r  = wn * 64 + (2 * njp + b_npart) * 8 + b_lrow;
                int ch = 2 * s + b_kpart;
                LDMATRIX_X4(bfr[2 * njp][0], bfr[2 * njp][1],
                            bfr[2 * njp + 1][0], bfr[2 * njp + 1][1],
                            sB + tile_off(r, ch));
            }
#pragma unroll
            for (int mi = 0; mi < 2; mi++)
#pragma unroll
                for (int nj = 0; nj < 8; nj++)
                    mma16816(acc[mi][nj], af[mi], bfr[nj]);
        }
    }

    // ---- fused LayerNorm epilogue ----
    float ps[2][2] = {{0.f, 0.f}, {0.f, 0.f}};
    float pq[2][2] = {{0.f, 0.f}, {0.f, 0.f}};
#pragma unroll
    for (int mi = 0; mi < 2; mi++)
#pragma unroll
        for (int nj = 0; nj < 8; nj++) {
            float c0 = acc[mi][nj][0], c1 = acc[mi][nj][1];
            float c2 = acc[mi][nj][2], c3 = acc[mi][nj][3];
            ps[mi][0] += c0 + c1;  pq[mi][0] += c0 * c0 + c1 * c1;
            ps[mi][1] += c2 + c3;  pq[mi][1] += c2 * c2 + c3 * c3;
        }
#pragma unroll
    for (int mi = 0; mi < 2; mi++)
#pragma unroll
        for (int rr = 0; rr < 2; rr++) {
            ps[mi][rr] += __shfl_xor_sync(0xffffffffu, ps[mi][rr], 1);
            ps[mi][rr] += __shfl_xor_sync(0xffffffffu, ps[mi][rr], 2);
            pq[mi][rr] += __shfl_xor_sync(0xffffffffu, pq[mi][rr], 1);
            pq[mi][rr] += __shfl_xor_sync(0xffffffffu, pq[mi][rr], 2);
        }
    if (tig == 0) {
#pragma unroll
        for (int mi = 0; mi < 2; mi++)
#pragma unroll
            for (int rr = 0; rr < 2; rr++) {
                int row = wm * 32 + mi * 16 + g + 8 * rr;
                rsum[row * 4 + wn] = ps[mi][rr];
                rsq [row * 4 + wn] = pq[mi][rr];
            }
    }
    __syncthreads();

    float mean[2][2], rstd[2][2];
#pragma unroll
    for (int mi = 0; mi < 2; mi++)
#pragma unroll
        for (int rr = 0; rr < 2; rr++) {
            int row = wm * 32 + mi * 16 + g + 8 * rr;
            float s  = rsum[row*4] + rsum[row*4+1] + rsum[row*4+2] + rsum[row*4+3];
            float qq = rsq [row*4] + rsq [row*4+1] + rsq [row*4+2] + rsq [row*4+3];
            float m = s * (1.f / 256.f);
            float v = qq * (1.f / 256.f) - m * m;
            mean[mi][rr] = m;
            rstd[mi][rr] = rsqrtf(v + 1e-5f);
        }

#pragma unroll
    for (int mi = 0; mi < 2; mi++) {
        int row0 = bm + wm * 32 + mi * 16 + g;
#pragma unroll
        for (int nj = 0; nj < 8; nj++) {
            int col = wn * 64 + nj * 8 + 2 * tig;
            float g0 = sg[col], g1 = sg[col + 1];
            float b0 = sb[col], b1 = sb[col + 1];
            float r0 = (acc[mi][nj][0] - mean[mi][0]) * rstd[mi][0] * g0 + b0;
            float r1 = (acc[mi][nj][1] - mean[mi][0]) * rstd[mi][0] * g1 + b1;
            float r2 = (acc[mi][nj][2] - mean[mi][1]) * rstd[mi][1] * g0 + b0;
            float r3 = (acc[mi][nj][3] - mean[mi][1]) * rstd[mi][1] * g1 + b1;
            if (FINAL) {
                size_t o0 = (size_t)row0 * N + col;
                size_t o1 = (size_t)(row0 + 8) * N + col;
                float2 x0 = *(const float2*)(resid + o0);
                float2 x1 = *(const float2*)(resid + o1);
                *(float2*)(outf + o0) = make_float2(r0 + x0.x, r1 + x0.y);
                *(float2*)(outf + o1) = make_float2(r2 + x1.x, r3 + x1.y);
            } else {
                *(uint32_t*)(outh + (size_t)row0 * N + col)       = pack_h2(r0, r1);
                *(uint32_t*)(outh + (size_t)(row0 + 8) * N + col) = pack_h2(r2, r3);
            }
        }
    }
}

// ---------------------------------------------------------------------------
// multi-job fp32 -> fp16 convert
// ---------------------------------------------------------------------------
struct ConvJob  { const float* in; hf* out; int n4; };
struct ConvJobs { ConvJob j[6]; };

__global__ __launch_bounds__(256) void hconv_multi(ConvJobs jobs)
{
    ConvJob jb = jobs.j[blockIdx.y];
    int i = blockIdx.x * 256 + threadIdx.x;
    if (i >= jb.n4) return;
    float4 f = ((const float4*)jb.in)[i];
    uint2 o;
    o.x = pack_h2(f.x, f.y);
    o.y = pack_h2(f.z, f.w);
    ((uint2*)jb.out)[i] = o;
}

// ---------------------------------------------------------------------------
// KV / Ksum chunked reduction over fp16 k/v (deterministic), then finalize
// ---------------------------------------------------------------------------
__global__ __launch_bounds__(256) void kv_reduce(
    const __half2* __restrict__ K2, const __half2* __restrict__ V2,
    float* __restrict__ kvp, float* __restrict__ ksp, int NH)
{
    int chunk = blockIdx.x, nh = blockIdx.y;
    int n = nh >> 3, h = nh & 7;
    int t = threadIdx.x, d = t & 31, eg = t >> 5;
    const int rows = LSEQ / NCHUNK;
    int s0 = chunk * rows;
    __shared__ __half2 Ks[16][16], Vs[16][16];
    float a0 = 0.f, a1 = 0.f, a2 = 0.f, a3 = 0.f, ks = 0.f;
    int ls = t >> 4, lp = t & 15;
    const int dh = d >> 1, dl = d & 1;

    for (int s = 0; s < rows; s += 16) {
        size_t off = (size_t)(n * LSEQ + s0 + s + ls) * 128 + h * 16 + lp;
        Ks[ls][lp] = K2[off];
        Vs[ls][lp] = V2[off];
        __syncthreads();
#pragma unroll
        for (int ss = 0; ss < 16; ss++) {
            __half2 kp = Ks[ss][dh];
            float kd = dl ? __high2float(kp) : __low2float(kp);
            if (eg == 0) ks += kd;
            __half2 v0 = Vs[ss][eg * 2];
            __half2 v1 = Vs[ss][eg * 2 + 1];
            a0 += kd * __low2float(v0);
            a1 += kd * __high2float(v0);
            a2 += kd * __low2float(v1);
            a3 += kd * __high2float(v1);
        }
        __syncthreads();
    }
    size_t pbase = ((size_t)(chunk * NH + nh) * 32 + d) * 32 + eg * 4;
    kvp[pbase + 0] = a0; kvp[pbase + 1] = a1;
    kvp[pbase + 2] = a2; kvp[pbase + 3] = a3;
    if (eg == 0) ksp[(size_t)(chunk * NH + nh) * 32 + d] = ks;
}

__global__ void kv_finalize(const float* __restrict__ kvp, const float* __restrict__ ksp,
                            float* __restrict__ kv, float* __restrict__ ksum, int NH)
{
    int i = blockIdx.x * blockDim.x + threadIdx.x;
    int tot_kv = NH * 1024, tot_ks = NH * 32;
    if (i < tot_kv) {
        float s = 0.f;
        for (int c = 0; c < NCHUNK; c++) s += kvp[(size_t)c * tot_kv + i];
        kv[i] = s;
    } else if (i < tot_kv + tot_ks) {
        int j = i - tot_kv;
        float s = 0.f;
        for (int c = 0; c < NCHUNK; c++) s += ksp[(size_t)c * tot_ks + j];
        ksum[j] = s;
    }
}

// ---------------------------------------------------------------------------
// attention output: one warp = one head, KV in registers, TOK tokens/block.
// ---------------------------------------------------------------------------
#define TOK 128

__global__ __launch_bounds__(256) void attn_out(
    const hf* __restrict__ Q, const float* __restrict__ KV,
    const float* __restrict__ Ksum, hf* __restrict__ mh)
{
    int w = threadIdx.x >> 5, lane = threadIdx.x & 31;
    int m0 = blockIdx.x * TOK;
    int n = m0 / LSEQ;
    int nh = n * NHEADS + w;

    const float* kvh = KV + (size_t)nh * 1024;
    float kvreg[32];
#pragma unroll
    for (int d = 0; d < 32; d++) kvreg[d] = kvh[d * 32 + lane];
    float ksl = Ksum[nh * 32 + lane];

    for (int t = 0; t < TOK; t++) {
        int m = m0 + t;
        size_t off = (size_t)m * CDIM + w * 32 + lane;
        float qv = __half2float(Q[off]);
        float z = qv * ksl;
#pragma unroll
        for (int o = 16; o; o >>= 1) z += __shfl_xor_sync(0xffffffffu, z, o);
        float Z = 1.f / (z + 1e-6f);
        float acc = 0.f;
#pragma unroll
        for (int d = 0; d < 32; d++)
            acc += __shfl_sync(0xffffffffu, qv, d) * kvreg[d];
        mh[off] = __float2half_rn(acc * Z);
    }
}

// ---------------------------------------------------------------------------
extern "C" void kernel_launch(void* const* d_in, const int* in_sizes, int n_in,
                              void* d_out, int out_size)
{
    const float* x    = (const float*)d_in[0];
    const float* src  = (const float*)d_in[1];
    const float* Wq   = (const float*)d_in[2];
    const float* Wk   = (const float*)d_in[3];
    const float* Wv   = (const float*)d_in[4];
    const float* Wm   = (const float*)d_in[5];
    const float* W1   = (const float*)d_in[6];
    const float* W2   = (const float*)d_in[7];
    const float* ln1g = (const float*)d_in[8];
    const float* ln1b = (const float*)d_in[9];
    const float* ln2g = (const float*)d_in[10];
    const float* ln2b = (const float*)d_in[11];

    const int C = CDIM;
    const int M = in_sizes[0] / C;
    const int Nb = M / LSEQ;
    const int NH = Nb * NHEADS;

    float *kvp, *ksp, *kv, *ksum;
    cudaGetSymbolAddress((void**)&kvp, g_kvp);
    cudaGetSymbolAddress((void**)&ksp, g_ksp);
    cudaGetSymbolAddress((void**)&kv, g_kv);
    cudaGetSymbolAddress((void**)&ksum, g_ksum);

    hf *qh, *kh, *vh, *xh, *sh, *mh, *t1h, *h1h;
    hf *wq, *wk, *wv, *wm, *w1, *w2;
    cudaGetSymbolAddress((void**)&qh, g_qh);
    cudaGetSymbolAddress((void**)&kh, g_kh);
    cudaGetSymbolAddress((void**)&vh, g_vh);
    cudaGetSymbolAddress((void**)&xh, g_xh);
    cudaGetSymbolAddress((void**)&sh, g_sh);
    cudaGetSymbolAddress((void**)&mh, g_mh);
    cudaGetSymbolAddress((void**)&t1h, g_t1h);
    cudaGetSymbolAddress((void**)&h1h, g_h1h);
    cudaGetSymbolAddress((void**)&wq, g_wq);
    cudaGetSymbolAddress((void**)&wk, g_wk);
    cudaGetSymbolAddress((void**)&wv, g_wv);
    cudaGetSymbolAddress((void**)&wm, g_wm);
    cudaGetSymbolAddress((void**)&w1, g_w1);
    cudaGetSymbolAddress((void**)&w2, g_w2);

    float* outp = (float*)d_out;

    const int DSMEM = STAGES * STAGE_BYTES;
    cudaFuncSetAttribute(gemm_mma<1, false>, cudaFuncAttributeMaxDynamicSharedMemorySize, DSMEM);
    cudaFuncSetAttribute(gemm_mma<1, true>,  cudaFuncAttributeMaxDynamicSharedMemorySize, DSMEM);
    cudaFuncSetAttribute(gemm_mma<2, false>, cudaFuncAttributeMaxDynamicSharedMemorySize, DSMEM);
    cudaFuncSetAttribute(gemm_ln<false>, cudaFuncAttributeMaxDynamicSharedMemorySize, LN_SMEM);
    cudaFuncSetAttribute(gemm_ln<true>,  cudaFuncAttributeMaxDynamicSharedMemorySize, LN_SMEM);

    // rope table + converts
    rope_init<<<1, 1024>>>();
    {
        int n4 = M * C / 4;
        ConvJobs ji = {};
        ji.j[0] = {x,   xh, n4};
        ji.j[1] = {src, sh, n4};
        hconv_multi<<<dim3((n4 + 255) / 256, 2), 256>>>(ji);

        int w4 = C * C / 4;
        ConvJobs jw = {};
        jw.j[0] = {Wq, wq, w4};
        jw.j[1] = {Wk, wk, w4};
        jw.j[2] = {Wv, wv, w4};
        jw.j[3] = {Wm, wm, w4};
        jw.j[4] = {W1, w1, 4 * w4};
        jw.j[5] = {W2, w2, 2 * w4};
        hconv_multi<<<dim3((4 * w4 + 255) / 256, 6), 256>>>(jw);
    }

    dim3 gq(C / 128, M / 128);
    // q, k projections (fused elu+1 + RoPE); v plain fp16
    gemm_mma<2, false><<<gq, 256, DSMEM>>>(xh, C, xh, C, C, wq, qh, M, C, C);
    gemm_mma<2, false><<<gq, 256, DSMEM>>>(sh, C, sh, C, C, wk, kh, M, C, C);
    gemm_mma<1, false><<<gq, 256, DSMEM>>>(sh, C, sh, C, C, wv, vh, M, C, C);

    // KV / Ksum
    kv_reduce<<<dim3(NCHUNK, NH), 256>>>((const __half2*)kh, (const __half2*)vh,
                                         kvp, ksp, NH);
    {
        int tot = NH * 1024 + NH * 32;
        kv_finalize<<<(tot + 255) / 256, 256>>>(kvp, ksp, kv, ksum, NH);
    }

    // attention out -> msg fp16 (register-resident KV)
    attn_out<<<M / TOK, 256>>>(qh, kv, ksum, mh);

    // t1 = LN1(msg @ Wm^T) fused -> fp16
    gemm_ln<false><<<M / 128, 512, LN_SMEM>>>(mh, wm, ln1g, ln1b, nullptr,
                                              nullptr, t1h, M, C);

    // h1 = relu([x, t1] @ W1^T) -> fp16   (N=512, K=512, Ksplit=256)
    gemm_mma<1, true><<<dim3(4, M / 128), 256, DSMEM>>>(
        xh, C, t1h, C, C, w1, h1h, M, 2 * C, 2 * C);

    // out = x + LN2(h1 @ W2^T) fused -> fp32
    gemm_ln<true><<<M / 128, 512, LN_SMEM>>>(h1h, w2, ln2g, ln2b, x,
                                             outp, nullptr, M, 2 * C);
}

// round 16
// speedup vs baseline: 1.0067x; 1.0067x over previous
#include <cuda_runtime.h>
#include <cuda_fp16.h>
#include <cstdint>
#include <math.h>

// ---------------------------------------------------------------------------
// RoPE-LoFTR encoder layer. mma.sync fp16 GEMMs (fp32 accum), ldmatrix,
// cp.async rings, RoPE fused in q/k epilogues (table-based), LayerNorms fused
// into the Wm and W2 GEMM epilogues, register-resident KV attention.
// N=4, L=16384 (128x128), C=256, NHEAD=8, D=32.
// ---------------------------------------------------------------------------

#define MAXM   65536
#define CDIM   256
#define LSEQ   16384
#define NHEADS 8
#define NCHUNK 32

typedef __half hf;

// fp32 buffers
__device__ float g_kvp[(size_t)NCHUNK * 32 * 32 * 32];
__device__ float g_ksp[(size_t)NCHUNK * 32 * 32];
__device__ float g_kv [(size_t)32 * 32 * 32];
__device__ float g_ksum[(size_t)32 * 32];
__device__ float2 g_rope[128 * 8];    // (pos-1, freq) -> {sin, cos}

// fp16 buffers
__device__ hf g_qh [(size_t)MAXM * CDIM];
__device__ hf g_kh [(size_t)MAXM * CDIM];
__device__ hf g_vh [(size_t)MAXM * CDIM];
__device__ hf g_xh [(size_t)MAXM * CDIM];
__device__ hf g_sh [(size_t)MAXM * CDIM];
__device__ hf g_mh [(size_t)MAXM * CDIM];
__device__ hf g_t1h[(size_t)MAXM * CDIM];
__device__ hf g_h1h[(size_t)MAXM * 2 * CDIM];
// fp16 weights
__device__ hf g_wq[CDIM * CDIM];
__device__ hf g_wk[CDIM * CDIM];
__device__ hf g_wv[CDIM * CDIM];
__device__ hf g_wm[CDIM * CDIM];
__device__ hf g_w1[2 * CDIM * 2 * CDIM];
__device__ hf g_w2[CDIM * 2 * CDIM];

// ---------------------------------------------------------------------------
#define CP_ASYNC16(dst, src) \
    asm volatile("cp.async.cg.shared.global [%0], [%1], 16;" \
                 :: "r"(dst), "l"(src) : "memory")
#define CP_COMMIT() asm volatile("cp.async.commit_group;" ::: "memory")
#define CP_WAIT(n)  asm volatile("cp.async.wait_group %0;" :: "n"(n) : "memory")

#define LDMATRIX_X4(r0, r1, r2, r3, addr) \
    asm volatile("ldmatrix.sync.aligned.m8n8.x4.shared.b16 {%0,%1,%2,%3}, [%4];" \
                 : "=r"(r0), "=r"(r1), "=r"(r2), "=r"(r3) : "r"(addr))

__device__ __forceinline__ uint32_t smem_u32(const void* p) {
    uint32_t a;
    asm("{ .reg .u64 t; cvta.to.shared.u64 t, %1; cvt.u32.u64 %0, t; }"
        : "=r"(a) : "l"(p));
    return a;
}

__device__ __forceinline__ void mma16816(float* c, const uint32_t* a,
                                         const uint32_t* b) {
    asm volatile(
        "mma.sync.aligned.m16n8k16.row.col.f32.f16.f16.f32 "
        "{%0,%1,%2,%3}, {%4,%5,%6,%7}, {%8,%9}, {%0,%1,%2,%3};"
        : "+f"(c[0]), "+f"(c[1]), "+f"(c[2]), "+f"(c[3])
        : "r"(a[0]), "r"(a[1]), "r"(a[2]), "r"(a[3]), "r"(b[0]), "r"(b[1]));
}

// smem tile rows x 32 fp16 (64B/row); 16B chunk swizzle: ch ^= (row>>1)&3
__device__ __forceinline__ uint32_t tile_off(int row, int ch) {
    return (uint32_t)(row * 64 + ((ch ^ ((row >> 1) & 3)) << 4));
}

__device__ __forceinline__ uint32_t pack_h2(float f0, float f1) {
    hf h0 = __float2half_rn(f0);
    hf h1 = __float2half_rn(f1);
    return (uint32_t)__half_as_ushort(h1) << 16 |
           (uint32_t)__half_as_ushort(h0);
}

// ---------------------------------------------------------------------------
// RoPE table init: angle = pos * exp(-f * ln(10000)/8), pos in 1..128.
// ---------------------------------------------------------------------------
__global__ void rope_init()
{
    int i = threadIdx.x;          // 0..1023
    int p = i >> 3, f = i & 7;
    float ang = (float)(p + 1) * expf(-(float)f * 1.1512925465f);
    float s, c;
    sincosf(ang, &s, &c);
    g_rope[i] = make_float2(s, c);
}

// ---------------------------------------------------------------------------
// GEMM: C[M,N] = A[M,K] @ B[N,K]^T; fp16 in, fp32 accum.
// Tile 128x128, BK=32, 256 threads (8 warps, 4m x 2n), 4-stage cp.async ring.
// OMODE 1: fp16 out (optional RELU). OMODE 2: elu+1 + RoPE, fp16 out (N=256).
// A switches to A2 at k=Ksplit (concat GEMM).
// ---------------------------------------------------------------------------
#define STAGES 4
#define STAGE_BYTES 16384

template <int OMODE, bool RELU>
__global__ __launch_bounds__(256) void gemm_mma(
    const hf* __restrict__ A, int lda,
    const hf* __restrict__ A2, int lda2, int Ksplit,
    const hf* __restrict__ B,
    hf* __restrict__ Ch,
    int M, int N, int K)
{
    extern __shared__ char smem[];

    const int tid  = threadIdx.x;
    const int lane = tid & 31;
    const int wid  = tid >> 5;
    const int g    = lane >> 2;
    const int tig  = lane & 3;
    const int wm   = wid & 3;
    const int wn   = wid >> 2;
    const int bm   = blockIdx.y * 128;
    const int bn   = blockIdx.x * 128;
    const int nkc  = K / 32;

    const int a_lrow  = lane & 15;
    const int a_khalf = lane >> 4;
    const int b_lrow  = lane & 7;
    const int b_kpart = (lane >> 3) & 1;
    const int b_npart = lane >> 4;

    float acc[2][8][4];
#pragma unroll
    for (int i = 0; i < 2; i++)
#pragma unroll
        for (int j = 0; j < 8; j++)
#pragma unroll
            for (int e = 0; e < 4; e++) acc[i][j][e] = 0.f;

    const int slot0 = tid, slot1 = tid + 256;

    auto issue = [&](int kc) {
        const int stg = kc & (STAGES - 1);
        const int kin = kc * 32;
        const hf* Asrc; int ald, koff;
        if (kin < Ksplit) { Asrc = A;  ald = lda;  koff = kin; }
        else              { Asrc = A2; ald = lda2; koff = kin - Ksplit; }

        uint32_t sA = smem_u32(smem + stg * STAGE_BYTES);
        uint32_t sB = sA + 8192;
        {
            int row = slot0 >> 2, ch = slot0 & 3;
            CP_ASYNC16(sA + tile_off(row, ch),
                       Asrc + (size_t)(bm + row) * ald + koff + ch * 8);
        }
        {
            int row = slot1 >> 2, ch = slot1 & 3;
            CP_ASYNC16(sA + tile_off(row, ch),
                       Asrc + (size_t)(bm + row) * ald + koff + ch * 8);
        }
        {
            int row = slot0 >> 2, ch = slot0 & 3;
            CP_ASYNC16(sB + tile_off(row, ch),
                       B + (size_t)(bn + row) * K + kin + ch * 8);
        }
        {
            int row = slot1 >> 2, ch = slot1 & 3;
            CP_ASYNC16(sB + tile_off(row, ch),
                       B + (size_t)(bn + row) * K + kin + ch * 8);
        }
        CP_COMMIT();
    };

    issue(0); issue(1); issue(2);

    for (int kc = 0; kc < nkc; kc++) {
        CP_WAIT(2);
        __syncthreads();
        if (kc + 3 < nkc) issue(kc + 3);
        else CP_COMMIT();

        const uint32_t sA = smem_u32(smem + (kc & (STAGES - 1)) * STAGE_BYTES);
        const uint32_t sB = sA + 8192;

#pragma unroll
        for (int s = 0; s < 2; s++) {
            uint32_t af[2][4];
#pragma unroll
            for (int mi = 0; mi < 2; mi++) {
                int r  = wm * 32 + mi * 16 + a_lrow;
                int ch = 2 * s + a_khalf;
                LDMATRIX_X4(af[mi][0], af[mi][1], af[mi][2], af[mi][3],
                            sA + tile_off(r, ch));
            }
            uint32_t bfr[8][2];
#pragma unroll
            for (int njp = 0; njp < 4; njp++) {
                int r  = wn * 64 + (2 * njp + b_npart) * 8 + b_lrow;
                int ch = 2 * s + b_kpart;
                LDMATRIX_X4(bfr[2 * njp][0], bfr[2 * njp][1],
                            bfr[2 * njp + 1][0], bfr[2 * njp + 1][1],
                            sB + tile_off(r, ch));
            }
#pragma unroll
            for (int mi = 0; mi < 2; mi++)
#pragma unroll
                for (int nj = 0; nj < 8; nj++)
                    mma16816(acc[mi][nj], af[mi], bfr[nj]);
        }
    }

    // epilogue
#pragma unroll
    for (int mi = 0; mi < 2; mi++) {
        int rbase = bm + wm * 32 + mi * 16 + g;
#pragma unroll
        for (int nj = 0; nj < 8; nj++) {
            int col = bn + wn * 64 + nj * 8 + 2 * tig;
            float c0 = acc[mi][nj][0], c1 = acc[mi][nj][1];
            float c2 = acc[mi][nj][2], c3 = acc[mi][nj][3];
            if (OMODE == 2) {
                // elu+1 then RoPE via table; (col, col+1) is a rotate pair
                int rem = col >> 1;            // 0..127 (N == 256)
                int tt  = rem & 15;
                int qf  = tt >> 1;
                bool odd = (tt & 1) != 0;
#pragma unroll
                for (int rr = 0; rr < 2; rr++) {
                    int r = rbase + rr * 8;
                    int l = r & (LSEQ - 1);
                    int p = odd ? (l & 127) : (l >> 7);
                    float2 sc = g_rope[p * 8 + qf];
                    float u0 = rr ? c2 : c0;
                    float u1 = rr ? c3 : c1;
                    float x0 = u0 > 0.f ? u0 + 1.f : __expf(u0);
                    float x1 = u1 > 0.f ? u1 + 1.f : __expf(u1);
                    *(uint32_t*)(Ch + (size_t)r * N + col) =
                        pack_h2(x0 * sc.y - x1 * sc.x, x1 * sc.y + x0 * sc.x);
                }
            } else {
                if (RELU) {
                    c0 = fmaxf(c0, 0.f); c1 = fmaxf(c1, 0.f);
                    c2 = fmaxf(c2, 0.f); c3 = fmaxf(c3, 0.f);
                }
                *(uint32_t*)(Ch + (size_t)rbase * N + col)       = pack_h2(c0, c1);
                *(uint32_t*)(Ch + (size_t)(rbase + 8) * N + col) = pack_h2(c2, c3);
            }
        }
    }
}

// ---------------------------------------------------------------------------
// GEMM + fused LayerNorm. C = LN(A @ B^T) over N=256 (full row per block).
// Tile 128x256, BK=32, 512 threads (16 warps, 4m x 4n), 4-stage cp.async.
// FINAL=false: write fp16 (LN1 -> t1h). FINAL=true: out = resid + LN, fp32.
// ---------------------------------------------------------------------------
#define LSTAGES 4
#define LSTAGE_BYTES 24576   // A 8KB + B 16KB
#define LN_SMEM (LSTAGES * LSTAGE_BYTES + 2 * 1024 + 2 * 2048)

template <bool FINAL>
__global__ __launch_bounds__(512) void gemm_ln(
    const hf* __restrict__ A, const hf* __restrict__ B,
    const float* __restrict__ gw, const float* __restrict__ bw,
    const float* __restrict__ resid,
    float* __restrict__ outf, hf* __restrict__ outh,
    int M, int K)
{
    extern __shared__ char smem[];
    float* sg   = (float*)(smem + LSTAGES * LSTAGE_BYTES);
    float* sb   = sg + 256;
    float* rsum = sb + 256;          // [128][4]
    float* rsq  = rsum + 512;        // [128][4]

    const int N = 256;
    const int tid  = threadIdx.x;
    const int lane = tid & 31;
    const int wid  = tid >> 5;
    const int g    = lane >> 2;
    const int tig  = lane & 3;
    const int wm   = wid & 3;
    const int wn   = wid >> 2;       // 0..3
    const int bm   = blockIdx.x * 128;
    const int nkc  = K / 32;

    const int a_lrow  = lane & 15;
    const int a_khalf = lane >> 4;
    const int b_lrow  = lane & 7;
    const int b_kpart = (lane >> 3) & 1;
    const int b_npart = lane >> 4;

    if (tid < 256) { sg[tid] = gw[tid]; sb[tid] = bw[tid]; }

    float acc[2][8][4];
#pragma unroll
    for (int i = 0; i < 2; i++)
#pragma unroll
        for (int j = 0; j < 8; j++)
#pragma unroll
            for (int e = 0; e < 4; e++) acc[i][j][e] = 0.f;

    auto issue = [&](int kc) {
        const int stg = kc & (LSTAGES - 1);
        const int kin = kc * 32;
        uint32_t sA = smem_u32(smem + stg * LSTAGE_BYTES);
        uint32_t sB = sA + 8192;
        {
            int row = tid >> 2, ch = tid & 3;
            CP_ASYNC16(sA + tile_off(row, ch),
                       A + (size_t)(bm + row) * K + kin + ch * 8);
        }
        {
            int row = tid >> 2, ch = tid & 3;
            CP_ASYNC16(sB + tile_off(row, ch),
                       B + (size_t)row * K + kin + ch * 8);
            int slot = tid + 512;
            int row2 = slot >> 2, ch2 = slot & 3;
            CP_ASYNC16(sB + tile_off(row2, ch2),
                       B + (size_t)row2 * K + kin + ch2 * 8);
        }
        CP_COMMIT();
    };

    issue(0); issue(1); issue(2);

    for (int kc = 0; kc < nkc; kc++) {
        CP_WAIT(2);
        __syncthreads();
        if (kc + 3 < nkc) issue(kc + 3);
        else CP_COMMIT();

        const uint32_t sA = smem_u32(smem + (kc & (LSTAGES - 1)) * LSTAGE_BYTES);
        const uint32_t sB = sA + 8192;

#pragma unroll
        for (int s = 0; s < 2; s++) {
            uint32_t af[2][4];
#pragma unroll
            for (int mi = 0; mi < 2; mi++) {
                int r  = wm * 32 + mi * 16 + a_lrow;
                int ch = 2 * s + a_khalf;
                LDMATRIX_X4(af[mi][0], af[mi][1], af[mi][2], af[mi][3],
                            sA + tile_off(r, ch));
            }
            uint32_t bfr[8][2];
#pragma unroll
            for (int njp = 0; njp < 4; njp++) {
                int r  = wn * 64 + (2 * njp + b_npart) * 8 + b_lrow;
                int ch = 2 * s + b_kpart;
                LDMATRIX_X4(bfr[2 * njp][0], bfr[2 * njp][1],
                            bfr[2 * njp + 1][0], bfr[2 * njp + 1][1],
                            sB + tile_off(r, ch));
            }
#pragma unroll
            for (int mi = 0; mi < 2; mi++)
#pragma unroll
                for (int nj = 0; nj < 8; nj++)
                    mma16816(acc[mi][nj], af[mi], bfr[nj]);
        }
    }

    // ---- fused LayerNorm epilogue ----
    float ps[2][2] = {{0.f, 0.f}, {0.f, 0.f}};
    float pq[2][2] = {{0.f, 0.f}, {0.f, 0.f}};
#pragma unroll
    for (int mi = 0; mi < 2; mi++)
#pragma unroll
        for (int nj = 0; nj < 8; nj++) {
            float c0 = acc[mi][nj][0], c1 = acc[mi][nj][1];
            float c2 = acc[mi][nj][2], c3 = acc[mi][nj][3];
            ps[mi][0] += c0 + c1;  pq[mi][0] += c0 * c0 + c1 * c1;
            ps[mi][1] += c2 + c3;  pq[mi][1] += c2 * c2 + c3 * c3;
        }
#pragma unroll
    for (int mi = 0; mi < 2; mi++)
#pragma unroll
        for (int rr = 0; rr < 2; rr++) {
            ps[mi][rr] += __shfl_xor_sync(0xffffffffu, ps[mi][rr], 1);
            ps[mi][rr] += __shfl_xor_sync(0xffffffffu, ps[mi][rr], 2);
            pq[mi][rr] += __shfl_xor_sync(0xffffffffu, pq[mi][rr], 1);
            pq[mi][rr] += __shfl_xor_sync(0xffffffffu, pq[mi][rr], 2);
        }
    if (tig == 0) {
#pragma unroll
        for (int mi = 0; mi < 2; mi++)
#pragma unroll
            for (int rr = 0; rr < 2; rr++) {
                int row = wm * 32 + mi * 16 + g + 8 * rr;
                rsum[row * 4 + wn] = ps[mi][rr];
                rsq [row * 4 + wn] = pq[mi][rr];
            }
    }
    __syncthreads();

    float mean[2][2], rstd[2][2];
#pragma unroll
    for (int mi = 0; mi < 2; mi++)
#pragma unroll
        for (int rr = 0; rr < 2; rr++) {
            int row = wm * 32 + mi * 16 + g + 8 * rr;
            float s  = rsum[row*4] + rsum[row*4+1] + rsum[row*4+2] + rsum[row*4+3];
            float qq = rsq [row*4] + rsq [row*4+1] + rsq [row*4+2] + rsq [row*4+3];
            float m = s * (1.f / 256.f);
            float v = qq * (1.f / 256.f) - m * m;
            mean[mi][rr] = m;
            rstd[mi][rr] = rsqrtf(v + 1e-5f);
        }

#pragma unroll
    for (int mi = 0; mi < 2; mi++) {
        int row0 = bm + wm * 32 + mi * 16 + g;
#pragma unroll
        for (int nj = 0; nj < 8; nj++) {
            int col = wn * 64 + nj * 8 + 2 * tig;
            float g0 = sg[col], g1 = sg[col + 1];
            float b0 = sb[col], b1 = sb[col + 1];
            float r0 = (acc[mi][nj][0] - mean[mi][0]) * rstd[mi][0] * g0 + b0;
            float r1 = (acc[mi][nj][1] - mean[mi][0]) * rstd[mi][0] * g1 + b1;
            float r2 = (acc[mi][nj][2] - mean[mi][1]) * rstd[mi][1] * g0 + b0;
            float r3 = (acc[mi][nj][3] - mean[mi][1]) * rstd[mi][1] * g1 + b1;
            if (FINAL) {
                size_t o0 = (size_t)row0 * N + col;
                size_t o1 = (size_t)(row0 + 8) * N + col;
                float2 x0 = *(const float2*)(resid + o0);
                float2 x1 = *(const float2*)(resid + o1);
                *(float2*)(outf + o0) = make_float2(r0 + x0.x, r1 + x0.y);
                *(float2*)(outf + o1) = make_float2(r2 + x1.x, r3 + x1.y);
            } else {
                *(uint32_t*)(outh + (size_t)row0 * N + col)       = pack_h2(r0, r1);
                *(uint32_t*)(outh + (size_t)(row0 + 8) * N + col) = pack_h2(r2, r3);
            }
        }
    }
}

// ---------------------------------------------------------------------------
// multi-job fp32 -> fp16 convert
// ---------------------------------------------------------------------------
struct ConvJob  { const float* in; hf* out; int n4; };
struct ConvJobs { ConvJob j[6]; };

__global__ __launch_bounds__(256) void hconv_multi(ConvJobs jobs)
{
    ConvJob jb = jobs.j[blockIdx.y];
    int i = blockIdx.x * 256 + threadIdx.x;
    if (i >= jb.n4) return;
    float4 f = ((const float4*)jb.in)[i];
    uint2 o;
    o.x = pack_h2(f.x, f.y);
    o.y = pack_h2(f.z, f.w);
    ((uint2*)jb.out)[i] = o;
}

// ---------------------------------------------------------------------------
// KV / Ksum chunked reduction over fp16 k/v (deterministic), then finalize
// ---------------------------------------------------------------------------
__global__ __launch_bounds__(256) void kv_reduce(
    const __half2* __restrict__ K2, const __half2* __restrict__ V2,
    float* __restrict__ kvp, float* __restrict__ ksp, int NH)
{
    int chunk = blockIdx.x, nh = blockIdx.y;
    int n = nh >> 3, h = nh & 7;
    int t = threadIdx.x, d = t & 31, eg = t >> 5;
    const int rows = LSEQ / NCHUNK;
    int s0 = chunk * rows;
    __shared__ __half2 Ks[16][16], Vs[16][16];
    float a0 = 0.f, a1 = 0.f, a2 = 0.f, a3 = 0.f, ks = 0.f;
    int ls = t >> 4, lp = t & 15;
    const int dh = d >> 1, dl = d & 1;

    for (int s = 0; s < rows; s += 16) {
        size_t off = (size_t)(n * LSEQ + s0 + s + ls) * 128 + h * 16 + lp;
        Ks[ls][lp] = K2[off];
        Vs[ls][lp] = V2[off];
        __syncthreads();
#pragma unroll
        for (int ss = 0; ss < 16; ss++) {
            __half2 kp = Ks[ss][dh];
            float kd = dl ? __high2float(kp) : __low2float(kp);
            if (eg == 0) ks += kd;
            __half2 v0 = Vs[ss][eg * 2];
            __half2 v1 = Vs[ss][eg * 2 + 1];
            a0 += kd * __low2float(v0);
            a1 += kd * __high2float(v0);
            a2 += kd * __low2float(v1);
            a3 += kd * __high2float(v1);
        }
        __syncthreads();
    }
    size_t pbase = ((size_t)(chunk * NH + nh) * 32 + d) * 32 + eg * 4;
    kvp[pbase + 0] = a0; kvp[pbase + 1] = a1;
    kvp[pbase + 2] = a2; kvp[pbase + 3] = a3;
    if (eg == 0) ksp[(size_t)(chunk * NH + nh) * 32 + d] = ks;
}

__global__ void kv_finalize(const float* __restrict__ kvp, const float* __restrict__ ksp,
                            float* __restrict__ kv, float* __restrict__ ksum, int NH)
{
    int i = blockIdx.x * blockDim.x + threadIdx.x;
    int tot_kv = NH * 1024, tot_ks = NH * 32;
    if (i < tot_kv) {
        float s = 0.f;
        for (int c = 0; c < NCHUNK; c++) s += kvp[(size_t)c * tot_kv + i];
        kv[i] = s;
    } else if (i < tot_kv + tot_ks) {
        int j = i - tot_kv;
        float s = 0.f;
        for (int c = 0; c < NCHUNK; c++) s += ksp[(size_t)c * tot_ks + j];
        ksum[j] = s;
    }
}

// ---------------------------------------------------------------------------
// attention output: one warp = one head, KV in registers, TOK tokens/block.
// ---------------------------------------------------------------------------
#define TOK 128

__global__ __launch_bounds__(256) void attn_out(
    const hf* __restrict__ Q, const float* __restrict__ KV,
    const float* __restrict__ Ksum, hf* __restrict__ mh)
{
    int w = threadIdx.x >> 5, lane = threadIdx.x & 31;
    int m0 = blockIdx.x * TOK;
    int n = m0 / LSEQ;
    int nh = n * NHEADS + w;

    const float* kvh = KV + (size_t)nh * 1024;
    float kvreg[32];
#pragma unroll
    for (int d = 0; d < 32; d++) kvreg[d] = kvh[d * 32 + lane];
    float ksl = Ksum[nh * 32 + lane];

    for (int t = 0; t < TOK; t++) {
        int m = m0 + t;
        size_t off = (size_t)m * CDIM + w * 32 + lane;
        float qv = __half2float(Q[off]);
        float z = qv * ksl;
#pragma unroll
        for (int o = 16; o; o >>= 1) z += __shfl_xor_sync(0xffffffffu, z, o);
        float Z = 1.f / (z + 1e-6f);
        float acc = 0.f;
#pragma unroll
        for (int d = 0; d < 32; d++)
            acc += __shfl_sync(0xffffffffu, qv, d) * kvreg[d];
        mh[off] = __float2half_rn(acc * Z);
    }
}

// ---------------------------------------------------------------------------
extern "C" void kernel_launch(void* const* d_in, const int* in_sizes, int n_in,
                              void* d_out, int out_size)
{
    const float* x    = (const float*)d_in[0];
    const float* src  = (const float*)d_in[1];
    const float* Wq   = (const float*)d_in[2];
    const float* Wk   = (const float*)d_in[3];
    const float* Wv   = (const float*)d_in[4];
    const float* Wm   = (const float*)d_in[5];
    const float* W1   = (const float*)d_in[6];
    const float* W2   = (const float*)d_in[7];
    const float* ln1g = (const float*)d_in[8];
    const float* ln1b = (const float*)d_in[9];
    const float* ln2g = (const float*)d_in[10];
    const float* ln2b = (const float*)d_in[11];

    const int C = CDIM;
    const int M = in_sizes[0] / C;
    const int Nb = M / LSEQ;
    const int NH = Nb * NHEADS;

    float *kvp, *ksp, *kv, *ksum;
    cudaGetSymbolAddress((void**)&kvp, g_kvp);
    cudaGetSymbolAddress((void**)&ksp, g_ksp);
    cudaGetSymbolAddress((void**)&kv, g_kv);
    cudaGetSymbolAddress((void**)&ksum, g_ksum);

    hf *qh, *kh, *vh, *xh, *sh, *mh, *t1h, *h1h;
    hf *wq, *wk, *wv, *wm, *w1, *w2;
    cudaGetSymbolAddress((void**)&qh, g_qh);
    cudaGetSymbolAddress((void**)&kh, g_kh);
    cudaGetSymbolAddress((void**)&vh, g_vh);
    cudaGetSymbolAddress((void**)&xh, g_xh);
    cudaGetSymbolAddress((void**)&sh, g_sh);
    cudaGetSymbolAddress((void**)&mh, g_mh);
    cudaGetSymbolAddress((void**)&t1h, g_t1h);
    cudaGetSymbolAddress((void**)&h1h, g_h1h);
    cudaGetSymbolAddress((void**)&wq, g_wq);
    cudaGetSymbolAddress((void**)&wk, g_wk);
    cudaGetSymbolAddress((void**)&wv, g_wv);
    cudaGetSymbolAddress((void**)&wm, g_wm);
    cudaGetSymbolAddress((void**)&w1, g_w1);
    cudaGetSymbolAddress((void**)&w2, g_w2);

    float* outp = (float*)d_out;

    const int DSMEM = STAGES * STAGE_BYTES;
    cudaFuncSetAttribute(gemm_mma<1, false>, cudaFuncAttributeMaxDynamicSharedMemorySize, DSMEM);
    cudaFuncSetAttribute(gemm_mma<1, true>,  cudaFuncAttributeMaxDynamicSharedMemorySize, DSMEM);
    cudaFuncSetAttribute(gemm_mma<2, false>, cudaFuncAttributeMaxDynamicSharedMemorySize, DSMEM);
    cudaFuncSetAttribute(gemm_ln<false>, cudaFuncAttributeMaxDynamicSharedMemorySize, LN_SMEM);
    cudaFuncSetAttribute(gemm_ln<true>,  cudaFuncAttributeMaxDynamicSharedMemorySize, LN_SMEM);

    // rope table + converts
    rope_init<<<1, 1024>>>();
    {
        int n4 = M * C / 4;
        ConvJobs ji = {};
        ji.j[0] = {x,   xh, n4};
        ji.j[1] = {src, sh, n4};
        hconv_multi<<<dim3((n4 + 255) / 256, 2), 256>>>(ji);

        int w4 = C * C / 4;
        ConvJobs jw = {};
        jw.j[0] = {Wq, wq, w4};
        jw.j[1] = {Wk, wk, w4};
        jw.j[2] = {Wv, wv, w4};
        jw.j[3] = {Wm, wm, w4};
        jw.j[4] = {W1, w1, 4 * w4};
        jw.j[5] = {W2, w2, 2 * w4};
        hconv_multi<<<dim3((4 * w4 + 255) / 256, 6), 256>>>(jw);
    }

    dim3 gq(C / 128, M / 128);
    // q, k projections (fused elu+1 + RoPE); v plain fp16
    gemm_mma<2, false><<<gq, 256, DSMEM>>>(xh, C, xh, C, C, wq, qh, M, C, C);
    gemm_mma<2, false><<<gq, 256, DSMEM>>>(sh, C, sh, C, C, wk, kh, M, C, C);
    gemm_mma<1, false><<<gq, 256, DSMEM>>>(sh, C, sh, C, C, wv, vh, M, C, C);

    // KV / Ksum
    kv_reduce<<<dim3(NCHUNK, NH), 256>>>((const __half2*)kh, (const __half2*)vh,
                                         kvp, ksp, NH);
    {
        int tot = NH * 1024 + NH * 32;
        kv_finalize<<<(tot + 255) / 256, 256>>>(kvp, ksp, kv, ksum, NH);
    }

    // attention out -> msg fp16 (register-resident KV)
    attn_out<<<M / TOK, 256>>>(qh, kv, ksum, mh);

    // t1 = LN1(msg @ Wm^T) fused -> fp16
    gemm_ln<false><<<M / 128, 512, LN_SMEM>>>(mh, wm, ln1g, ln1b, nullptr,
                                              nullptr, t1h, M, C);

    // h1 = relu([x, t1] @ W1^T) -> fp16   (N=512, K=512, Ksplit=256)
    gemm_mma<1, true><<<dim3(4, M / 128), 256, DSMEM>>>(
        xh, C, t1h, C, C, w1, h1h, M, 2 * C, 2 * C);

    // out = x + LN2(h1 @ W2^T) fused -> fp32
    gemm_ln<true><<<M / 128, 512, LN_SMEM>>>(h1h, w2, ln2g, ln2b, x,
                                             outp, nullptr, M, 2 * C);
}